// round 14
// baseline (speedup 1.0000x reference)
#include <cuda_runtime.h>
#include <cuda_fp16.h>
#include <math.h>

// Problem constants: N=8, C=3, R=8, P=512*512, n_iter=3
#define P_    262144
#define P4_   65536        // float4 / point-group count per plane
#define EPS_  1e-10f
#define NB    440          // total blocks (8 n-groups x 55); 3/SM co-resident
#define BPN   55
#define NTHR  128
#define RSTR  129          // reduction smem stride (conflict-free)
#define CHUNK 256          // point-groups per claimed chunk (2 block-iterations)
#define NCHUNK (P4_ / CHUNK)   // 256 chunks per n

// ---- device globals (no allocations allowed) ----
__device__ float    g_stats[3 * 544];     // per iter, per n: [0,8) sum, [8,32) XD, [32,68) gram-tri
__device__ float    g_meanx[NB * 3];
__device__ unsigned g_count;
__device__ unsigned g_sense;
__device__ unsigned g_ctr[3 * 8];         // per (pass, n) chunk counters
__device__ unsigned g_sctr[8];            // scale-pass chunk counters
// fp16 Dt scratch: [n][rp][point4] planes; uint4 = 4 points x (r=2rp, r=2rp+1)
__device__ uint4    g_dt4[(size_t)32 * P4_];

__device__ __forceinline__ int triIdx(int r, int r2) {   // r <= r2
    return r * 8 - (r * (r - 1)) / 2 + (r2 - r);
}
__device__ __forceinline__ float getc(const float4& v, int j) {
    return j == 0 ? v.x : j == 1 ? v.y : j == 2 ? v.z : v.w;
}
__device__ __forceinline__ float hsel(unsigned u, int hi) {
    __half2 h = *reinterpret_cast<__half2*>(&u);
    return hi ? __high2float(h) : __low2float(h);
}
__device__ __forceinline__ unsigned h2bits(__half2 h) {
    return *reinterpret_cast<unsigned*>(&h);
}
__device__ __forceinline__ float4 h4tof4(unsigned a_, unsigned b_) {
    __half2 a = *reinterpret_cast<__half2*>(&a_);
    __half2 b = *reinterpret_cast<__half2*>(&b_);
    float2 fa = __half22float2(a), fb = __half22float2(b);
    return make_float4(fa.x, fa.y, fb.x, fb.y);
}
__device__ __forceinline__ unsigned ld_acq(unsigned* p) {
    unsigned v;
    asm volatile("ld.acquire.gpu.u32 %0, [%1];" : "=r"(v) : "l"(p) : "memory");
    return v;
}
// grid-wide sense-reversal barrier; all NB blocks co-resident by construction
__device__ __forceinline__ void gridsync() {
    __threadfence();
    __syncthreads();
    if (threadIdx.x == 0) {
        unsigned s0 = ld_acq(&g_sense);
        unsigned old = atomicAdd(&g_count, 1u);
        if (old == NB - 1) {
            atomicExch(&g_count, 0u);
            __threadfence();
            atomicAdd(&g_sense, 1u);
        } else {
            while (ld_acq(&g_sense) == s0) __nanosleep(64);
        }
    }
    __syncthreads();
}

// ---------------------------------------------------------------------------
// k_init0: deterministically reset ALL persistent barrier/counter/stat state.
// Runs as its own launch before k_all, so an interrupted prior launch can
// never poison the next one.
// ---------------------------------------------------------------------------
__global__ void k_init0() {
    int t = threadIdx.x;
    if (t == 0) { g_count = 0u; g_sense = 0u; }
    if (t < 24) g_ctr[t] = 0u;
    if (t < 8)  g_sctr[t] = 0u;
    for (int i = t; i < 3 * 544; i += blockDim.x) g_stats[i] = 0.f;
}

// iterA: StS, tauD, x0(own n), cnst(own n). Redundant per block.
__device__ __forceinline__ void do_iterA(int tid, int n,
        const float* sS, const float* sMX, const float* f_own, const float* acc_own,
        float* cn_own, float* sStS, float* x0c, float* sh_tauD, float lam, float gam) {
    if (tid < 64) {
        int r = tid >> 3, r2 = tid & 7;
        float a = 0.f;
        #pragma unroll
        for (int c = 0; c < 3; c++) a += sS[c * 8 + r] * sS[c * 8 + r2];
        sStS[tid] = a;
    }
    __syncthreads();
    if (tid == 0) {
        float s = 0.f;
        #pragma unroll
        for (int r = 0; r < 8; r++) s += sStS[r * 8 + r];
        *sh_tauD = 1.f / s;
    }
    __syncthreads();
    float tauD = *sh_tauD;
    if (tid < 3) {
        float acc = sMX[n * 3 + tid];
        #pragma unroll
        for (int r = 0; r < 8; r++) acc += sS[tid * 8 + r] * f_own[r] * acc_own[r];
        x0c[tid] = acc * (1.f / (float)P_);
    }
    __syncthreads();
    if (tid < 8) {
        int r = tid;
        float bb = 0.f;
        #pragma unroll
        for (int c = 0; c < 3; c++) bb += sS[c * 8 + r] * x0c[c];
        cn_own[r] = tauD * bb - lam * gam * tauD * sqrtf(sStS[r * 8 + r]);
    }
    __syncthreads();
}

// ---------------------------------------------------------------------------
// run_pass: fused D-update + prox + stats, DYNAMIC chunked work stealing.
//   Chunks of CHUNK point-groups claimed from a per-(pass,n) atomic counter.
//   X via cp.async 2-stage, Dt fp16 uint4 register prefetch, in-place output
//   pack, half2 pairwise stats, sqrt(tauD) fold.
// ---------------------------------------------------------------------------
template<int FIRST>
__device__ __forceinline__ void run_pass(
    const float4* __restrict__ Xp, uint4* __restrict__ Dq4,
    float* red, unsigned* ctr, unsigned* sh_chunk, int tid,
    const float* sS, const float* f_own, const float* cn_own, float tauD,
    float* dst)
{
    float4* sx = reinterpret_cast<float4*>(red);    // X stage area (overlaid on red)

    float Sp[24], fr[8], cn[8];
    const float sq = sqrtf(tauD);
    #pragma unroll
    for (int k = 0; k < 24; k++) Sp[k] = sq * sS[k];
    #pragma unroll
    for (int r = 0; r < 8; r++) { fr[r] = f_own[r]; cn[r] = cn_own[r]; }

    const __half2 hz = __floats2half2_rn(0.f, 0.f);
    __half2 a_s2[8], a_x2[24], a_g2[36];
    #pragma unroll
    for (int k = 0; k < 8; k++)  a_s2[k] = hz;
    #pragma unroll
    for (int k = 0; k < 24; k++) a_x2[k] = hz;
    #pragma unroll
    for (int k = 0; k < 36; k++) a_g2[k] = hz;

    auto issueX = [&](int i, int stage) {
        #pragma unroll
        for (int c = 0; c < 3; c++) {
            unsigned dstA = (unsigned)__cvta_generic_to_shared(
                &sx[(stage * 3 + c) * NTHR + tid]);
            asm volatile("cp.async.cg.shared.global [%0], [%1], 16;"
                         :: "r"(dstA), "l"(&Xp[i + c * P4_]) : "memory");
        }
        asm volatile("cp.async.commit_group;" ::: "memory");
    };

    // body: compute one point-group from staged X + prefetched Dt.
    auto body = [&](int i, int stage, uint4* dq, int waitn) {
        if (waitn == 1) asm volatile("cp.async.wait_group 1;" ::: "memory");
        else            asm volatile("cp.async.wait_group 0;" ::: "memory");
        float4 xv0 = sx[(stage * 3 + 0) * NTHR + tid];
        float4 xv1 = sx[(stage * 3 + 1) * NTHR + tid];
        float4 xv2 = sx[(stage * 3 + 2) * NTHR + tid];
        float vprev[8], xprev0, xprev1, xprev2;
        #pragma unroll
        for (int j = 0; j < 4; j++) {
            const float x0 = getc(xv0, j), x1 = getc(xv1, j), x2 = getc(xv2, j);
            float tt0 = sq * x0, tt1 = sq * x1, tt2 = sq * x2;
            float de[8], v[8];
            if (!FIRST) {
                #pragma unroll
                for (int rp = 0; rp < 4; rp++) {
                    unsigned wa = (j < 2) ? dq[rp].x : dq[rp].y;
                    unsigned wb = (j < 2) ? dq[rp].z : dq[rp].w;
                    de[2 * rp]     = fr[2 * rp]     * hsel(wa, j & 1);
                    de[2 * rp + 1] = fr[2 * rp + 1] * hsel(wb, j & 1);
                }
                #pragma unroll
                for (int r = 0; r < 8; r++) {
                    tt0 += Sp[r] * de[r];
                    tt1 += Sp[8 + r] * de[r];
                    tt2 += Sp[16 + r] * de[r];
                }
            }
            #pragma unroll
            for (int r = 0; r < 8; r++) {
                float w = FIRST ? cn[r] : (de[r] + cn[r]);
                float val = w - Sp[r] * tt0 - Sp[8 + r] * tt1 - Sp[16 + r] * tt2;
                v[r] = fmaxf(val, 0.f);
            }
            if ((j & 1) == 0) {
                #pragma unroll
                for (int r = 0; r < 8; r++) vprev[r] = v[r];
                xprev0 = x0; xprev1 = x1; xprev2 = x2;
            } else {
                __half2 p[8];
                #pragma unroll
                for (int r = 0; r < 8; r++) p[r] = __floats2half2_rn(vprev[r], v[r]);
                #pragma unroll
                for (int rp = 0; rp < 4; rp++) {
                    unsigned pa = h2bits(p[2 * rp]);
                    unsigned pb = h2bits(p[2 * rp + 1]);
                    if (j == 1) { dq[rp].x = pa; dq[rp].z = pb; }
                    else        { dq[rp].y = pa; dq[rp].w = pb; }
                }
                __half2 px0 = __floats2half2_rn(xprev0, x0);
                __half2 px1 = __floats2half2_rn(xprev1, x1);
                __half2 px2 = __floats2half2_rn(xprev2, x2);
                #pragma unroll
                for (int r = 0; r < 8; r++) {
                    a_s2[r]      = __hadd2(a_s2[r], p[r]);
                    a_x2[r]      = __hfma2(px0, p[r], a_x2[r]);
                    a_x2[8 + r]  = __hfma2(px1, p[r], a_x2[8 + r]);
                    a_x2[16 + r] = __hfma2(px2, p[r], a_x2[16 + r]);
                }
                int gi = 0;
                #pragma unroll
                for (int r = 0; r < 8; r++)
                    #pragma unroll
                    for (int r2 = r; r2 < 8; r2++) {
                        a_g2[gi] = __hfma2(p[r], p[r2], a_g2[gi]);
                        gi++;
                    }
            }
        }
        #pragma unroll
        for (int rp = 0; rp < 4; rp++) Dq4[i + rp * P4_] = dq[rp];
    };

    // ---- dynamic chunk loop ----
    while (true) {
        __syncthreads();                       // stage reuse + sh_chunk guard
        if (tid == 0) *sh_chunk = atomicAdd(ctr, 1u);
        __syncthreads();
        unsigned c = *sh_chunk;
        if (c >= NCHUNK) break;
        int iA = (int)c * CHUNK + tid;
        int iB = iA + NTHR;
        issueX(iA, 0);
        issueX(iB, 1);
        uint4 dA[4], dB[4];
        if (!FIRST) {
            #pragma unroll
            for (int rp = 0; rp < 4; rp++) dA[rp] = Dq4[iA + rp * P4_];
            #pragma unroll
            for (int rp = 0; rp < 4; rp++) dB[rp] = Dq4[iB + rp * P4_];
        }
        body(iA, 0, dA, 1);
        body(iB, 1, dB, 0);
    }

    // ---- flush: half2 -> f32, then smem transpose (stride RSTR) ----
    __syncthreads();   // all cp.async drained (wait_group 0 in last body)
    #pragma unroll
    for (int k = 0; k < 8; k++) {
        float2 f = __half22float2(a_s2[k]);
        red[k * RSTR + tid] = f.x + f.y;
    }
    #pragma unroll
    for (int k = 0; k < 24; k++) {
        float2 f = __half22float2(a_x2[k]);
        red[(8 + k) * RSTR + tid] = f.x + f.y;
    }
    #pragma unroll
    for (int k = 0; k < 36; k++) {
        float2 f = __half22float2(a_g2[k]);
        red[(32 + k) * RSTR + tid] = f.x + f.y;
    }
    __syncthreads();
    if (tid < 68) {
        const float* row = &red[tid * RSTR];
        float s0 = 0.f, s1 = 0.f, s2 = 0.f, s3 = 0.f;
        #pragma unroll 8
        for (int t = 0; t < NTHR; t += 4) {
            s0 += row[t]; s1 += row[t + 1]; s2 += row[t + 2]; s3 += row[t + 3];
        }
        atomicAdd(&dst[tid], (s0 + s1) + (s2 + s3));
    }
}

__global__ void __launch_bounds__(NTHR, 3)
k_all(const float* __restrict__ X, const float* __restrict__ Sin,
      const float* __restrict__ gamma_, const float* __restrict__ lam_,
      float* __restrict__ out) {
    extern __shared__ float red[];           // [68 * RSTR]; doubles as X stage area
    const int tid   = threadIdx.x;
    const int b     = blockIdx.x;
    const int n     = b / BPN;
    const int local = b % BPN;
    const int s4    = (P4_ * local) / BPN;   // static range for meanx only
    const int e4    = (P4_ * (local + 1)) / BPN;
    const int lane  = tid & 31, wid = tid >> 5;

    __shared__ float sS[24], sMX[24], f_own[8], cn_own[8], acc_own[8], x0c[3];
    __shared__ float sh_tauD, sh_lam, sh_gam;
    __shared__ float s_scl[64], s_sums[64], s_gt[64], s_tr[64];
    __shared__ float s_gram[8][8][8], s_x0[24], s_G[192], s_Sg[24], s_n3[8], s_tauS;
    __shared__ float sStS[64];
    __shared__ float sred[12];
    __shared__ unsigned sh_chunk;

    if (tid < 24) sS[tid] = Sin[tid];
    if (tid == 24) sh_gam = fabsf(gamma_[0]);
    if (tid == 25) sh_lam = fabsf(lam_[0]);
    if (tid < 8) { f_own[tid] = 0.f; acc_own[tid] = 0.f; }

    const float4* Xp = reinterpret_cast<const float4*>(X) + (size_t)n * 3 * P4_;
    uint4* Dq4 = g_dt4 + (size_t)n * 4 * P4_;
    float4* Dpout = reinterpret_cast<float4*>(out + 48) + (size_t)n * 8 * P4_;

    // ---- meanX partials over static own range ----
    {
        float m0 = 0.f, m1 = 0.f, m2 = 0.f;
        for (int i = s4 + tid; i < e4; i += NTHR) {
            float4 a = Xp[i], bb = Xp[i + P4_], c = Xp[i + 2 * P4_];
            m0 += a.x + a.y + a.z + a.w;
            m1 += bb.x + bb.y + bb.z + bb.w;
            m2 += c.x + c.y + c.z + c.w;
        }
        #pragma unroll
        for (int o = 16; o; o >>= 1) {
            m0 += __shfl_xor_sync(~0u, m0, o);
            m1 += __shfl_xor_sync(~0u, m1, o);
            m2 += __shfl_xor_sync(~0u, m2, o);
        }
        if (lane == 0) { sred[wid * 3 + 0] = m0; sred[wid * 3 + 1] = m1; sred[wid * 3 + 2] = m2; }
        __syncthreads();
        if (tid < 3) {
            float s = 0.f;
            #pragma unroll
            for (int w = 0; w < 4; w++) s += sred[w * 3 + tid];
            g_meanx[b * 3 + tid] = s;
        }
    }

    gridsync();   // meanx partials visible (stats/counters zeroed by k_init0)

    if (tid < 24) {
        int nn = tid / 3, cc = tid % 3;
        float s = 0.f;
        for (int j = 0; j < BPN; j++) s += g_meanx[(nn * BPN + j) * 3 + cc];
        sMX[tid] = s;
    }
    __syncthreads();
    const float lam = sh_lam, gam = sh_gam;

    do_iterA(tid, n, sS, sMX, f_own, acc_own, cn_own, sStS, x0c, &sh_tauD, lam, gam);

    for (int it = 0; it < 3; it++) {
        float* dst = &g_stats[it * 544 + n * 68];
        unsigned* ctr = &g_ctr[it * 8 + n];
        if (it == 0) run_pass<1>(Xp, Dq4, red, ctr, &sh_chunk, tid, sS, f_own, cn_own, sh_tauD, dst);
        else         run_pass<0>(Xp, Dq4, red, ctr, &sh_chunk, tid, sS, f_own, cn_own, sh_tauD, dst);

        gridsync();   // stats of this iteration complete

        // ================= iterB (redundant per block) =================
        {
            const int last = (it == 2);
            const float* st = &g_stats[it * 544];
            const float tauD = sh_tauD;
            if (tid < 64) {
                int nn = tid >> 3, r = tid & 7;
                float gu = st[nn * 68 + 32 + triIdx(r, r)];
                float L2 = sqrtf(gu);
                float t = L2 - lam * tauD * sqrtf(sStS[r * 8 + r]);
                float scl = fmaxf(t, 0.f) / L2 + EPS_;        // faithful to source
                s_scl[tid] = scl;
                float su = scl * st[nn * 68 + r];
                s_sums[tid] = su;
                s_gt[tid] = gam * su + scl * L2;
                s_tr[tid] = scl * scl * gu;
            }
            __syncthreads();
            for (int idx = tid; idx < 512; idx += NTHR) {
                int nn = idx >> 6, r = (idx >> 3) & 7, r2 = idx & 7;
                int lo = min(r, r2), hi = max(r, r2);
                s_gram[nn][r][r2] = s_scl[nn * 8 + r] * s_scl[nn * 8 + r2] *
                                    st[nn * 68 + 32 + triIdx(lo, hi)];
            }
            __syncthreads();
            if (tid < 24) {
                int nn = tid / 3, c = tid % 3;
                float a = sMX[tid];
                #pragma unroll
                for (int r = 0; r < 8; r++) a += sS[c * 8 + r] * s_sums[nn * 8 + r];
                a *= (1.f / (float)P_);
                s_x0[tid] = a;
                if (last && b == 0) out[tid] = a;
            }
            if (tid == 64) {
                float s = 0.f;
                for (int k = 0; k < 64; k++) s += s_tr[k];
                s_tauS = 8.f / s;
            }
            __syncthreads();
            for (int idx = tid; idx < 192; idx += NTHR) {
                int nn = idx / 24, c = (idx / 8) % 3, r = idx & 7;
                float g = s_scl[nn * 8 + r] * st[nn * 68 + 8 + c * 8 + r];
                #pragma unroll
                for (int r2 = 0; r2 < 8; r2++) g += sS[c * 8 + r2] * s_gram[nn][r2][r];
                g -= s_x0[nn * 3 + c] * s_sums[nn * 8 + r];
                s_G[idx] = g;
            }
            __syncthreads();
            if (tid < 24) {
                int c = tid / 8, r = tid & 7;
                float mg = 0.f;
                #pragma unroll
                for (int nn = 0; nn < 8; nn++) mg += s_G[nn * 24 + c * 8 + r];
                mg *= 0.125f;
                s_Sg[tid] = sS[c * 8 + r] - s_tauS * mg;
            }
            __syncthreads();
            if (tid < 8) {
                int r = tid;
                float dn = 0.f;
                #pragma unroll
                for (int nn = 0; nn < 8; nn++) dn += s_gt[nn * 8 + r];
                dn *= 0.125f;
                float n2 = 0.f;
                #pragma unroll
                for (int c = 0; c < 3; c++) n2 += s_Sg[c * 8 + r] * s_Sg[c * 8 + r];
                n2 = sqrtf(n2);
                float t = n2 - lam * s_tauS * dn;
                float sclS = fmaxf(t, 0.f) / (n2 + EPS_);
                float sn[3]; float n3 = 0.f;
                #pragma unroll
                for (int c = 0; c < 3; c++) { sn[c] = s_Sg[c * 8 + r] * sclS; n3 += sn[c] * sn[c]; }
                n3 = sqrtf(n3);
                s_n3[r] = n3;
                float inv = 1.f / (n3 + EPS_);
                #pragma unroll
                for (int c = 0; c < 3; c++) {
                    float nv = sn[c] * inv;
                    sS[c * 8 + r] = nv;
                    if (last && b == 0) out[24 + c * 8 + r] = nv;
                }
            }
            __syncthreads();
            if (tid < 8) {
                f_own[tid]   = s_scl[n * 8 + tid] * (s_n3[tid] + EPS_);
                acc_own[tid] = st[n * 68 + tid];
            }
            __syncthreads();
            if (!last)
                do_iterA(tid, n, sS, sMX, f_own, acc_own, cn_own, sStS, x0c, &sh_tauD, lam, gam);
        }
    }

    // ====== final scale pass: out = f * fp16(Dt_it2), dynamic chunks. ======
    {
        float fs[8];
        #pragma unroll
        for (int r = 0; r < 8; r++) fs[r] = f_own[r];
        auto sbody = [&](int i, uint4* dq) {
            #pragma unroll
            for (int rp = 0; rp < 4; rp++) {
                float4 va = h4tof4(dq[rp].x, dq[rp].y);
                float4 vb = h4tof4(dq[rp].z, dq[rp].w);
                float fa = fs[2 * rp], fb = fs[2 * rp + 1];
                va.x *= fa; va.y *= fa; va.z *= fa; va.w *= fa;
                vb.x *= fb; vb.y *= fb; vb.z *= fb; vb.w *= fb;
                __stcs(&Dpout[i + (2 * rp) * P4_], va);
                __stcs(&Dpout[i + (2 * rp + 1) * P4_], vb);
            }
        };
        unsigned* ctr = &g_sctr[n];
        while (true) {
            __syncthreads();
            if (tid == 0) sh_chunk = atomicAdd(ctr, 1u);
            __syncthreads();
            unsigned c = sh_chunk;
            if (c >= NCHUNK) break;
            int iA = (int)c * CHUNK + tid;
            int iB = iA + NTHR;
            uint4 dA[4], dB[4];
            #pragma unroll
            for (int rp = 0; rp < 4; rp++) dA[rp] = Dq4[iA + rp * P4_];
            #pragma unroll
            for (int rp = 0; rp < 4; rp++) dB[rp] = Dq4[iB + rp * P4_];
            sbody(iA, dA);
            sbody(iB, dB);
        }
    }
}

extern "C" void kernel_launch(void* const* d_in, const int* in_sizes, int n_in,
                              void* d_out, int out_size) {
    const float* X     = (const float*)d_in[0];
    const float* S     = (const float*)d_in[1];
    const float* gamma = (const float*)d_in[2];
    const float* lam   = (const float*)d_in[3];
    float* out = (float*)d_out;
    const int smem_bytes = 68 * RSTR * 4;    // 35,088 B (reduction buffer / X stages)
    k_init0<<<1, 512>>>();                   // deterministic state reset every launch
    k_all<<<NB, NTHR, smem_bytes>>>(X, S, gamma, lam, out);
}

// round 15
// speedup vs baseline: 1.0212x; 1.0212x over previous
#include <cuda_runtime.h>
#include <cuda_fp16.h>
#include <math.h>

// Problem constants: N=8, C=3, R=8, P=512*512, n_iter=3
#define P_    262144
#define P4_   65536        // float4 / point-group count per plane
#define EPS_  1e-10f
#define NB    440          // total blocks (8 n-groups x 55); 3/SM co-resident
#define BPN   55
#define NTHR  128
#define RSTR  129          // reduction smem stride (conflict-free)
#define CHUNK 256          // point-groups per claimed chunk (2 block-iterations)
#define NCHUNK (P4_ / CHUNK)   // 256 chunks per n

// ---- device globals (no allocations allowed) ----
__device__ float    g_stats[3 * 544];     // per iter, per n: [0,8) sum, [8,32) XD, [32,68) gram-tri
__device__ float    g_meanx[NB * 3];
__device__ unsigned g_count;
__device__ unsigned g_sense;
__device__ unsigned g_ctr[3 * 8];         // per (pass, n) chunk counters
__device__ unsigned g_sctr[8];            // scale-pass chunk counters
// fp16 Dt scratch: [n][rp][point4] planes; uint4 = 4 points x (r=2rp, r=2rp+1)
__device__ uint4    g_dt4[(size_t)32 * P4_];

__device__ __forceinline__ int triIdx(int r, int r2) {   // r <= r2
    return r * 8 - (r * (r - 1)) / 2 + (r2 - r);
}
__device__ __forceinline__ float getc(const float4& v, int j) {
    return j == 0 ? v.x : j == 1 ? v.y : j == 2 ? v.z : v.w;
}
__device__ __forceinline__ float hsel(unsigned u, int hi) {
    __half2 h = *reinterpret_cast<__half2*>(&u);
    return hi ? __high2float(h) : __low2float(h);
}
__device__ __forceinline__ unsigned h2bits(__half2 h) {
    return *reinterpret_cast<unsigned*>(&h);
}
__device__ __forceinline__ float4 h4tof4(unsigned a_, unsigned b_) {
    __half2 a = *reinterpret_cast<__half2*>(&a_);
    __half2 b = *reinterpret_cast<__half2*>(&b_);
    float2 fa = __half22float2(a), fb = __half22float2(b);
    return make_float4(fa.x, fa.y, fb.x, fb.y);
}
__device__ __forceinline__ unsigned ld_acq(unsigned* p) {
    unsigned v;
    asm volatile("ld.acquire.gpu.u32 %0, [%1];" : "=r"(v) : "l"(p) : "memory");
    return v;
}
// grid-wide sense-reversal barrier; all NB blocks co-resident by construction
__device__ __forceinline__ void gridsync() {
    __threadfence();
    __syncthreads();
    if (threadIdx.x == 0) {
        unsigned s0 = ld_acq(&g_sense);
        unsigned old = atomicAdd(&g_count, 1u);
        if (old == NB - 1) {
            atomicExch(&g_count, 0u);
            __threadfence();
            atomicAdd(&g_sense, 1u);
        } else {
            while (ld_acq(&g_sense) == s0) __nanosleep(64);
        }
    }
    __syncthreads();
}

// ---------------------------------------------------------------------------
// k_init0: deterministically reset ALL persistent barrier/counter/stat state.
// Runs as its own launch before k_all, so an interrupted prior launch can
// never poison the next one.
// ---------------------------------------------------------------------------
__global__ void k_init0() {
    int t = threadIdx.x;
    if (t == 0) { g_count = 0u; g_sense = 0u; }
    if (t < 24) g_ctr[t] = 0u;
    if (t < 8)  g_sctr[t] = 0u;
    for (int i = t; i < 3 * 544; i += blockDim.x) g_stats[i] = 0.f;
}

// iterA: StS, tauD, x0(own n), cnst(own n). Redundant per block.
__device__ __forceinline__ void do_iterA(int tid, int n,
        const float* sS, const float* sMX, const float* f_own, const float* acc_own,
        float* cn_own, float* sStS, float* x0c, float* sh_tauD, float lam, float gam) {
    if (tid < 64) {
        int r = tid >> 3, r2 = tid & 7;
        float a = 0.f;
        #pragma unroll
        for (int c = 0; c < 3; c++) a += sS[c * 8 + r] * sS[c * 8 + r2];
        sStS[tid] = a;
    }
    __syncthreads();
    if (tid == 0) {
        float s = 0.f;
        #pragma unroll
        for (int r = 0; r < 8; r++) s += sStS[r * 8 + r];
        *sh_tauD = 1.f / s;
    }
    __syncthreads();
    float tauD = *sh_tauD;
    if (tid < 3) {
        float acc = sMX[n * 3 + tid];
        #pragma unroll
        for (int r = 0; r < 8; r++) acc += sS[tid * 8 + r] * f_own[r] * acc_own[r];
        x0c[tid] = acc * (1.f / (float)P_);
    }
    __syncthreads();
    if (tid < 8) {
        int r = tid;
        float bb = 0.f;
        #pragma unroll
        for (int c = 0; c < 3; c++) bb += sS[c * 8 + r] * x0c[c];
        cn_own[r] = tauD * bb - lam * gam * tauD * sqrtf(sStS[r * 8 + r]);
    }
    __syncthreads();
}

// ---------------------------------------------------------------------------
// run_pass: fused D-update + prox + stats, DYNAMIC chunked work stealing.
//   Chunks of CHUNK point-groups claimed from a per-(pass,n) atomic counter.
//   X via cp.async 2-stage, Dt fp16 uint4 register prefetch, in-place output
//   pack, half2 pairwise stats, sqrt(tauD) fold.
// ---------------------------------------------------------------------------
template<int FIRST>
__device__ __forceinline__ void run_pass(
    const float4* __restrict__ Xp, uint4* __restrict__ Dq4,
    float* red, unsigned* ctr, unsigned* sh_chunk, int tid,
    const float* sS, const float* f_own, const float* cn_own, float tauD,
    float* dst)
{
    float4* sx = reinterpret_cast<float4*>(red);    // X stage area (overlaid on red)

    float Sp[24], fr[8], cn[8];
    const float sq = sqrtf(tauD);
    #pragma unroll
    for (int k = 0; k < 24; k++) Sp[k] = sq * sS[k];
    #pragma unroll
    for (int r = 0; r < 8; r++) { fr[r] = f_own[r]; cn[r] = cn_own[r]; }

    const __half2 hz = __floats2half2_rn(0.f, 0.f);
    __half2 a_s2[8], a_x2[24], a_g2[36];
    #pragma unroll
    for (int k = 0; k < 8; k++)  a_s2[k] = hz;
    #pragma unroll
    for (int k = 0; k < 24; k++) a_x2[k] = hz;
    #pragma unroll
    for (int k = 0; k < 36; k++) a_g2[k] = hz;

    auto issueX = [&](int i, int stage) {
        #pragma unroll
        for (int c = 0; c < 3; c++) {
            unsigned dstA = (unsigned)__cvta_generic_to_shared(
                &sx[(stage * 3 + c) * NTHR + tid]);
            asm volatile("cp.async.cg.shared.global [%0], [%1], 16;"
                         :: "r"(dstA), "l"(&Xp[i + c * P4_]) : "memory");
        }
        asm volatile("cp.async.commit_group;" ::: "memory");
    };

    // body: compute one point-group from staged X + prefetched Dt.
    auto body = [&](int i, int stage, uint4* dq, int waitn) {
        if (waitn == 1) asm volatile("cp.async.wait_group 1;" ::: "memory");
        else            asm volatile("cp.async.wait_group 0;" ::: "memory");
        float4 xv0 = sx[(stage * 3 + 0) * NTHR + tid];
        float4 xv1 = sx[(stage * 3 + 1) * NTHR + tid];
        float4 xv2 = sx[(stage * 3 + 2) * NTHR + tid];
        float vprev[8], xprev0, xprev1, xprev2;
        #pragma unroll
        for (int j = 0; j < 4; j++) {
            const float x0 = getc(xv0, j), x1 = getc(xv1, j), x2 = getc(xv2, j);
            float tt0 = sq * x0, tt1 = sq * x1, tt2 = sq * x2;
            float de[8], v[8];
            if (!FIRST) {
                #pragma unroll
                for (int rp = 0; rp < 4; rp++) {
                    unsigned wa = (j < 2) ? dq[rp].x : dq[rp].y;
                    unsigned wb = (j < 2) ? dq[rp].z : dq[rp].w;
                    de[2 * rp]     = fr[2 * rp]     * hsel(wa, j & 1);
                    de[2 * rp + 1] = fr[2 * rp + 1] * hsel(wb, j & 1);
                }
                #pragma unroll
                for (int r = 0; r < 8; r++) {
                    tt0 += Sp[r] * de[r];
                    tt1 += Sp[8 + r] * de[r];
                    tt2 += Sp[16 + r] * de[r];
                }
            }
            #pragma unroll
            for (int r = 0; r < 8; r++) {
                float w = FIRST ? cn[r] : (de[r] + cn[r]);
                float val = w - Sp[r] * tt0 - Sp[8 + r] * tt1 - Sp[16 + r] * tt2;
                v[r] = fmaxf(val, 0.f);
            }
            if ((j & 1) == 0) {
                #pragma unroll
                for (int r = 0; r < 8; r++) vprev[r] = v[r];
                xprev0 = x0; xprev1 = x1; xprev2 = x2;
            } else {
                __half2 p[8];
                #pragma unroll
                for (int r = 0; r < 8; r++) p[r] = __floats2half2_rn(vprev[r], v[r]);
                #pragma unroll
                for (int rp = 0; rp < 4; rp++) {
                    unsigned pa = h2bits(p[2 * rp]);
                    unsigned pb = h2bits(p[2 * rp + 1]);
                    if (j == 1) { dq[rp].x = pa; dq[rp].z = pb; }
                    else        { dq[rp].y = pa; dq[rp].w = pb; }
                }
                __half2 px0 = __floats2half2_rn(xprev0, x0);
                __half2 px1 = __floats2half2_rn(xprev1, x1);
                __half2 px2 = __floats2half2_rn(xprev2, x2);
                #pragma unroll
                for (int r = 0; r < 8; r++) {
                    a_s2[r]      = __hadd2(a_s2[r], p[r]);
                    a_x2[r]      = __hfma2(px0, p[r], a_x2[r]);
                    a_x2[8 + r]  = __hfma2(px1, p[r], a_x2[8 + r]);
                    a_x2[16 + r] = __hfma2(px2, p[r], a_x2[16 + r]);
                }
                int gi = 0;
                #pragma unroll
                for (int r = 0; r < 8; r++)
                    #pragma unroll
                    for (int r2 = r; r2 < 8; r2++) {
                        a_g2[gi] = __hfma2(p[r], p[r2], a_g2[gi]);
                        gi++;
                    }
            }
        }
        #pragma unroll
        for (int rp = 0; rp < 4; rp++) Dq4[i + rp * P4_] = dq[rp];
    };

    // ---- dynamic chunk loop ----
    while (true) {
        __syncthreads();                       // stage reuse + sh_chunk guard
        if (tid == 0) *sh_chunk = atomicAdd(ctr, 1u);
        __syncthreads();
        unsigned c = *sh_chunk;
        if (c >= NCHUNK) break;
        int iA = (int)c * CHUNK + tid;
        int iB = iA + NTHR;
        issueX(iA, 0);
        issueX(iB, 1);
        uint4 dA[4], dB[4];
        if (!FIRST) {
            #pragma unroll
            for (int rp = 0; rp < 4; rp++) dA[rp] = Dq4[iA + rp * P4_];
            #pragma unroll
            for (int rp = 0; rp < 4; rp++) dB[rp] = Dq4[iB + rp * P4_];
        }
        body(iA, 0, dA, 1);
        body(iB, 1, dB, 0);
    }

    // ---- flush: half2 -> f32, then smem transpose (stride RSTR) ----
    __syncthreads();   // all cp.async drained (wait_group 0 in last body)
    #pragma unroll
    for (int k = 0; k < 8; k++) {
        float2 f = __half22float2(a_s2[k]);
        red[k * RSTR + tid] = f.x + f.y;
    }
    #pragma unroll
    for (int k = 0; k < 24; k++) {
        float2 f = __half22float2(a_x2[k]);
        red[(8 + k) * RSTR + tid] = f.x + f.y;
    }
    #pragma unroll
    for (int k = 0; k < 36; k++) {
        float2 f = __half22float2(a_g2[k]);
        red[(32 + k) * RSTR + tid] = f.x + f.y;
    }
    __syncthreads();
    if (tid < 68) {
        const float* row = &red[tid * RSTR];
        float s0 = 0.f, s1 = 0.f, s2 = 0.f, s3 = 0.f;
        #pragma unroll 8
        for (int t = 0; t < NTHR; t += 4) {
            s0 += row[t]; s1 += row[t + 1]; s2 += row[t + 2]; s3 += row[t + 3];
        }
        atomicAdd(&dst[tid], (s0 + s1) + (s2 + s3));
    }
}

__global__ void __launch_bounds__(NTHR, 3)
k_all(const float* __restrict__ X, const float* __restrict__ Sin,
      const float* __restrict__ gamma_, const float* __restrict__ lam_,
      float* __restrict__ out) {
    extern __shared__ float red[];           // [68 * RSTR]; doubles as X stage area
    const int tid   = threadIdx.x;
    const int b     = blockIdx.x;
    const int n     = b / BPN;
    const int local = b % BPN;
    const int s4    = (P4_ * local) / BPN;   // static range for meanx only
    const int e4    = (P4_ * (local + 1)) / BPN;
    const int lane  = tid & 31, wid = tid >> 5;

    __shared__ float sS[24], sMX[24], f_own[8], cn_own[8], acc_own[8], x0c[3];
    __shared__ float sh_tauD, sh_lam, sh_gam;
    __shared__ float s_scl[64], s_sums[64], s_gt[64], s_tr[64];
    __shared__ float s_gram[8][8][8], s_x0[24], s_G[192], s_Sg[24], s_n3[8], s_tauS;
    __shared__ float sStS[64];
    __shared__ float sred[12];
    __shared__ unsigned sh_chunk;

    if (tid < 24) sS[tid] = Sin[tid];
    if (tid == 24) sh_gam = fabsf(gamma_[0]);
    if (tid == 25) sh_lam = fabsf(lam_[0]);
    if (tid < 8) { f_own[tid] = 0.f; acc_own[tid] = 0.f; }

    const float4* Xp = reinterpret_cast<const float4*>(X) + (size_t)n * 3 * P4_;
    uint4* Dq4 = g_dt4 + (size_t)n * 4 * P4_;
    float4* Dpout = reinterpret_cast<float4*>(out + 48) + (size_t)n * 8 * P4_;

    // ---- meanX partials over static own range ----
    {
        float m0 = 0.f, m1 = 0.f, m2 = 0.f;
        for (int i = s4 + tid; i < e4; i += NTHR) {
            float4 a = Xp[i], bb = Xp[i + P4_], c = Xp[i + 2 * P4_];
            m0 += a.x + a.y + a.z + a.w;
            m1 += bb.x + bb.y + bb.z + bb.w;
            m2 += c.x + c.y + c.z + c.w;
        }
        #pragma unroll
        for (int o = 16; o; o >>= 1) {
            m0 += __shfl_xor_sync(~0u, m0, o);
            m1 += __shfl_xor_sync(~0u, m1, o);
            m2 += __shfl_xor_sync(~0u, m2, o);
        }
        if (lane == 0) { sred[wid * 3 + 0] = m0; sred[wid * 3 + 1] = m1; sred[wid * 3 + 2] = m2; }
        __syncthreads();
        if (tid < 3) {
            float s = 0.f;
            #pragma unroll
            for (int w = 0; w < 4; w++) s += sred[w * 3 + tid];
            g_meanx[b * 3 + tid] = s;
        }
    }

    gridsync();   // meanx partials visible (stats/counters zeroed by k_init0)

    if (tid < 24) {
        int nn = tid / 3, cc = tid % 3;
        float s = 0.f;
        for (int j = 0; j < BPN; j++) s += g_meanx[(nn * BPN + j) * 3 + cc];
        sMX[tid] = s;
    }
    __syncthreads();
    const float lam = sh_lam, gam = sh_gam;

    do_iterA(tid, n, sS, sMX, f_own, acc_own, cn_own, sStS, x0c, &sh_tauD, lam, gam);

    for (int it = 0; it < 3; it++) {
        float* dst = &g_stats[it * 544 + n * 68];
        unsigned* ctr = &g_ctr[it * 8 + n];
        if (it == 0) run_pass<1>(Xp, Dq4, red, ctr, &sh_chunk, tid, sS, f_own, cn_own, sh_tauD, dst);
        else         run_pass<0>(Xp, Dq4, red, ctr, &sh_chunk, tid, sS, f_own, cn_own, sh_tauD, dst);

        gridsync();   // stats of this iteration complete

        // ================= iterB (redundant per block) =================
        {
            const int last = (it == 2);
            const float* st = &g_stats[it * 544];
            const float tauD = sh_tauD;
            if (tid < 64) {
                int nn = tid >> 3, r = tid & 7;
                float gu = st[nn * 68 + 32 + triIdx(r, r)];
                float L2 = sqrtf(gu);
                float t = L2 - lam * tauD * sqrtf(sStS[r * 8 + r]);
                float scl = fmaxf(t, 0.f) / L2 + EPS_;        // faithful to source
                s_scl[tid] = scl;
                float su = scl * st[nn * 68 + r];
                s_sums[tid] = su;
                s_gt[tid] = gam * su + scl * L2;
                s_tr[tid] = scl * scl * gu;
            }
            __syncthreads();
            for (int idx = tid; idx < 512; idx += NTHR) {
                int nn = idx >> 6, r = (idx >> 3) & 7, r2 = idx & 7;
                int lo = min(r, r2), hi = max(r, r2);
                s_gram[nn][r][r2] = s_scl[nn * 8 + r] * s_scl[nn * 8 + r2] *
                                    st[nn * 68 + 32 + triIdx(lo, hi)];
            }
            __syncthreads();
            if (tid < 24) {
                int nn = tid / 3, c = tid % 3;
                float a = sMX[tid];
                #pragma unroll
                for (int r = 0; r < 8; r++) a += sS[c * 8 + r] * s_sums[nn * 8 + r];
                a *= (1.f / (float)P_);
                s_x0[tid] = a;
                if (last && b == 0) out[tid] = a;
            }
            if (tid == 64) {
                float s = 0.f;
                for (int k = 0; k < 64; k++) s += s_tr[k];
                s_tauS = 8.f / s;
            }
            __syncthreads();
            for (int idx = tid; idx < 192; idx += NTHR) {
                int nn = idx / 24, c = (idx / 8) % 3, r = idx & 7;
                float g = s_scl[nn * 8 + r] * st[nn * 68 + 8 + c * 8 + r];
                #pragma unroll
                for (int r2 = 0; r2 < 8; r2++) g += sS[c * 8 + r2] * s_gram[nn][r2][r];
                g -= s_x0[nn * 3 + c] * s_sums[nn * 8 + r];
                s_G[idx] = g;
            }
            __syncthreads();
            if (tid < 24) {
                int c = tid / 8, r = tid & 7;
                float mg = 0.f;
                #pragma unroll
                for (int nn = 0; nn < 8; nn++) mg += s_G[nn * 24 + c * 8 + r];
                mg *= 0.125f;
                s_Sg[tid] = sS[c * 8 + r] - s_tauS * mg;
            }
            __syncthreads();
            if (tid < 8) {
                int r = tid;
                float dn = 0.f;
                #pragma unroll
                for (int nn = 0; nn < 8; nn++) dn += s_gt[nn * 8 + r];
                dn *= 0.125f;
                float n2 = 0.f;
                #pragma unroll
                for (int c = 0; c < 3; c++) n2 += s_Sg[c * 8 + r] * s_Sg[c * 8 + r];
                n2 = sqrtf(n2);
                float t = n2 - lam * s_tauS * dn;
                float sclS = fmaxf(t, 0.f) / (n2 + EPS_);
                float sn[3]; float n3 = 0.f;
                #pragma unroll
                for (int c = 0; c < 3; c++) { sn[c] = s_Sg[c * 8 + r] * sclS; n3 += sn[c] * sn[c]; }
                n3 = sqrtf(n3);
                s_n3[r] = n3;
                float inv = 1.f / (n3 + EPS_);
                #pragma unroll
                for (int c = 0; c < 3; c++) {
                    float nv = sn[c] * inv;
                    sS[c * 8 + r] = nv;
                    if (last && b == 0) out[24 + c * 8 + r] = nv;
                }
            }
            __syncthreads();
            if (tid < 8) {
                f_own[tid]   = s_scl[n * 8 + tid] * (s_n3[tid] + EPS_);
                acc_own[tid] = st[n * 68 + tid];
            }
            __syncthreads();
            if (!last)
                do_iterA(tid, n, sS, sMX, f_own, acc_own, cn_own, sStS, x0c, &sh_tauD, lam, gam);
        }
    }

    // ====== final scale pass: out = f * fp16(Dt_it2), dynamic chunks. ======
    {
        float fs[8];
        #pragma unroll
        for (int r = 0; r < 8; r++) fs[r] = f_own[r];
        auto sbody = [&](int i, uint4* dq) {
            #pragma unroll
            for (int rp = 0; rp < 4; rp++) {
                float4 va = h4tof4(dq[rp].x, dq[rp].y);
                float4 vb = h4tof4(dq[rp].z, dq[rp].w);
                float fa = fs[2 * rp], fb = fs[2 * rp + 1];
                va.x *= fa; va.y *= fa; va.z *= fa; va.w *= fa;
                vb.x *= fb; vb.y *= fb; vb.z *= fb; vb.w *= fb;
                __stcs(&Dpout[i + (2 * rp) * P4_], va);
                __stcs(&Dpout[i + (2 * rp + 1) * P4_], vb);
            }
        };
        unsigned* ctr = &g_sctr[n];
        while (true) {
            __syncthreads();
            if (tid == 0) sh_chunk = atomicAdd(ctr, 1u);
            __syncthreads();
            unsigned c = sh_chunk;
            if (c >= NCHUNK) break;
            int iA = (int)c * CHUNK + tid;
            int iB = iA + NTHR;
            uint4 dA[4], dB[4];
            #pragma unroll
            for (int rp = 0; rp < 4; rp++) dA[rp] = Dq4[iA + rp * P4_];
            #pragma unroll
            for (int rp = 0; rp < 4; rp++) dB[rp] = Dq4[iB + rp * P4_];
            sbody(iA, dA);
            sbody(iB, dB);
        }
    }
}

extern "C" void kernel_launch(void* const* d_in, const int* in_sizes, int n_in,
                              void* d_out, int out_size) {
    const float* X     = (const float*)d_in[0];
    const float* S     = (const float*)d_in[1];
    const float* gamma = (const float*)d_in[2];
    const float* lam   = (const float*)d_in[3];
    float* out = (float*)d_out;
    const int smem_bytes = 68 * RSTR * 4;    // 35,088 B (reduction buffer / X stages)
    k_init0<<<1, 512>>>();                   // deterministic state reset every launch
    k_all<<<NB, NTHR, smem_bytes>>>(X, S, gamma, lam, out);
}

// round 16
// speedup vs baseline: 1.0491x; 1.0273x over previous
#include <cuda_runtime.h>
#include <cuda_fp16.h>
#include <math.h>

// Problem constants: N=8, C=3, R=8, P=512*512, n_iter=3
#define P_    262144
#define P4_   65536        // float4 / point-group count per plane
#define EPS_  1e-10f
#define NB    440          // total blocks (8 n-groups x 55); 3/SM co-resident
#define BPN   55
#define NTHR  128
#define RSTR  129          // reduction smem stride (conflict-free)

// ---- device globals (no allocations allowed) ----
__device__ float    g_stats[3 * 544];     // per iter, per n: [0,8) sum, [8,32) XD, [32,68) gram-tri
__device__ float    g_meanx[NB * 3];
__device__ unsigned g_count;
__device__ unsigned g_sense;
// fp16 Dt scratch: [n][rp][point4] planes; uint4 = 4 points x (r=2rp, r=2rp+1)
__device__ uint4    g_dt4[(size_t)32 * P4_];

__device__ __forceinline__ int triIdx(int r, int r2) {   // r <= r2
    return r * 8 - (r * (r - 1)) / 2 + (r2 - r);
}
__device__ __forceinline__ float getc(const float4& v, int j) {
    return j == 0 ? v.x : j == 1 ? v.y : j == 2 ? v.z : v.w;
}
__device__ __forceinline__ float hsel(unsigned u, int hi) {
    __half2 h = *reinterpret_cast<__half2*>(&u);
    return hi ? __high2float(h) : __low2float(h);
}
__device__ __forceinline__ unsigned h2bits(__half2 h) {
    return *reinterpret_cast<unsigned*>(&h);
}
__device__ __forceinline__ float4 h4tof4(unsigned a_, unsigned b_) {
    __half2 a = *reinterpret_cast<__half2*>(&a_);
    __half2 b = *reinterpret_cast<__half2*>(&b_);
    float2 fa = __half22float2(a), fb = __half22float2(b);
    return make_float4(fa.x, fa.y, fb.x, fb.y);
}
__device__ __forceinline__ unsigned ld_acq(unsigned* p) {
    unsigned v;
    asm volatile("ld.acquire.gpu.u32 %0, [%1];" : "=r"(v) : "l"(p) : "memory");
    return v;
}
// grid-wide sense-reversal barrier; all NB blocks co-resident by construction
__device__ __forceinline__ void gridsync() {
    __threadfence();
    __syncthreads();
    if (threadIdx.x == 0) {
        unsigned s0 = ld_acq(&g_sense);
        unsigned old = atomicAdd(&g_count, 1u);
        if (old == NB - 1) {
            atomicExch(&g_count, 0u);
            __threadfence();
            atomicAdd(&g_sense, 1u);
        } else {
            while (ld_acq(&g_sense) == s0) __nanosleep(64);
        }
    }
    __syncthreads();
}

// ---------------------------------------------------------------------------
// k_init0: deterministically reset ALL persistent barrier/stat state each
// launch, so an interrupted prior replay can never poison the gridsync.
// ---------------------------------------------------------------------------
__global__ void k_init0() {
    int t = threadIdx.x;
    if (t == 0) { g_count = 0u; g_sense = 0u; }
    for (int i = t; i < 3 * 544; i += blockDim.x) g_stats[i] = 0.f;
}

// iterA: StS, tauD, x0(own n), cnst(own n). Redundant per block.
__device__ __forceinline__ void do_iterA(int tid, int n,
        const float* sS, const float* sMX, const float* f_own, const float* acc_own,
        float* cn_own, float* sStS, float* x0c, float* sh_tauD, float lam, float gam) {
    if (tid < 64) {
        int r = tid >> 3, r2 = tid & 7;
        float a = 0.f;
        #pragma unroll
        for (int c = 0; c < 3; c++) a += sS[c * 8 + r] * sS[c * 8 + r2];
        sStS[tid] = a;
    }
    __syncthreads();
    if (tid == 0) {
        float s = 0.f;
        #pragma unroll
        for (int r = 0; r < 8; r++) s += sStS[r * 8 + r];
        *sh_tauD = 1.f / s;
    }
    __syncthreads();
    float tauD = *sh_tauD;
    if (tid < 3) {
        float acc = sMX[n * 3 + tid];
        #pragma unroll
        for (int r = 0; r < 8; r++) acc += sS[tid * 8 + r] * f_own[r] * acc_own[r];
        x0c[tid] = acc * (1.f / (float)P_);
    }
    __syncthreads();
    if (tid < 8) {
        int r = tid;
        float bb = 0.f;
        #pragma unroll
        for (int c = 0; c < 3; c++) bb += sS[c * 8 + r] * x0c[c];
        cn_own[r] = tauD * bb - lam * gam * tauD * sqrtf(sStS[r * 8 + r]);
    }
    __syncthreads();
}

// ---------------------------------------------------------------------------
// run_pass: fused D-update + prox + stats (proven R12 configuration).
//   X pipelined global->smem via cp.async (2 stages, zero register cost),
//   Dt fp16 uint4 planes with register ping-pong prefetch, in-place output
//   pack, half2 pairwise stats, sqrt(tauD) fold.
//   FIRST=1: no Dt read (dq = pure output staging).
// ---------------------------------------------------------------------------
template<int FIRST>
__device__ __forceinline__ void run_pass(
    const float4* __restrict__ Xp, uint4* __restrict__ Dq4,
    float* red, int s4, int e4, int tid,
    const float* sS, const float* f_own, const float* cn_own, float tauD,
    float* dst)
{
    float4* sx = reinterpret_cast<float4*>(red);    // X stage area (overlaid on red)

    float Sp[24], fr[8], cn[8];
    const float sq = sqrtf(tauD);
    #pragma unroll
    for (int k = 0; k < 24; k++) Sp[k] = sq * sS[k];
    #pragma unroll
    for (int r = 0; r < 8; r++) { fr[r] = f_own[r]; cn[r] = cn_own[r]; }

    const __half2 hz = __floats2half2_rn(0.f, 0.f);
    __half2 a_s2[8], a_x2[24], a_g2[36];
    #pragma unroll
    for (int k = 0; k < 8; k++)  a_s2[k] = hz;
    #pragma unroll
    for (int k = 0; k < 24; k++) a_x2[k] = hz;
    #pragma unroll
    for (int k = 0; k < 36; k++) a_g2[k] = hz;

    auto issueX = [&](int i, int stage) {
        #pragma unroll
        for (int c = 0; c < 3; c++) {
            unsigned dstA = (unsigned)__cvta_generic_to_shared(
                &sx[(stage * 3 + c) * NTHR + tid]);
            asm volatile("cp.async.cg.shared.global [%0], [%1], 16;"
                         :: "r"(dstA), "l"(&Xp[i + c * P4_]) : "memory");
        }
        asm volatile("cp.async.commit_group;" ::: "memory");
    };

    auto body = [&](int i, int stage, uint4* dq) {
        asm volatile("cp.async.wait_group 1;" ::: "memory");
        float4 xv0 = sx[(stage * 3 + 0) * NTHR + tid];
        float4 xv1 = sx[(stage * 3 + 1) * NTHR + tid];
        float4 xv2 = sx[(stage * 3 + 2) * NTHR + tid];
        float vprev[8], xprev0, xprev1, xprev2;
        #pragma unroll
        for (int j = 0; j < 4; j++) {
            const float x0 = getc(xv0, j), x1 = getc(xv1, j), x2 = getc(xv2, j);
            float tt0 = sq * x0, tt1 = sq * x1, tt2 = sq * x2;
            float de[8], v[8];
            if (!FIRST) {
                #pragma unroll
                for (int rp = 0; rp < 4; rp++) {
                    unsigned wa = (j < 2) ? dq[rp].x : dq[rp].y;
                    unsigned wb = (j < 2) ? dq[rp].z : dq[rp].w;
                    de[2 * rp]     = fr[2 * rp]     * hsel(wa, j & 1);
                    de[2 * rp + 1] = fr[2 * rp + 1] * hsel(wb, j & 1);
                }
                #pragma unroll
                for (int r = 0; r < 8; r++) {
                    tt0 += Sp[r] * de[r];
                    tt1 += Sp[8 + r] * de[r];
                    tt2 += Sp[16 + r] * de[r];
                }
            }
            #pragma unroll
            for (int r = 0; r < 8; r++) {
                float w = FIRST ? cn[r] : (de[r] + cn[r]);
                float val = w - Sp[r] * tt0 - Sp[8 + r] * tt1 - Sp[16 + r] * tt2;
                v[r] = fmaxf(val, 0.f);
            }
            if ((j & 1) == 0) {
                #pragma unroll
                for (int r = 0; r < 8; r++) vprev[r] = v[r];
                xprev0 = x0; xprev1 = x1; xprev2 = x2;
            } else {
                __half2 p[8];
                #pragma unroll
                for (int r = 0; r < 8; r++) p[r] = __floats2half2_rn(vprev[r], v[r]);
                #pragma unroll
                for (int rp = 0; rp < 4; rp++) {
                    unsigned pa = h2bits(p[2 * rp]);
                    unsigned pb = h2bits(p[2 * rp + 1]);
                    if (j == 1) { dq[rp].x = pa; dq[rp].z = pb; }
                    else        { dq[rp].y = pa; dq[rp].w = pb; }
                }
                __half2 px0 = __floats2half2_rn(xprev0, x0);
                __half2 px1 = __floats2half2_rn(xprev1, x1);
                __half2 px2 = __floats2half2_rn(xprev2, x2);
                #pragma unroll
                for (int r = 0; r < 8; r++) {
                    a_s2[r]      = __hadd2(a_s2[r], p[r]);
                    a_x2[r]      = __hfma2(px0, p[r], a_x2[r]);
                    a_x2[8 + r]  = __hfma2(px1, p[r], a_x2[8 + r]);
                    a_x2[16 + r] = __hfma2(px2, p[r], a_x2[16 + r]);
                }
                int gi = 0;
                #pragma unroll
                for (int r = 0; r < 8; r++)
                    #pragma unroll
                    for (int r2 = r; r2 < 8; r2++) {
                        a_g2[gi] = __hfma2(p[r], p[r2], a_g2[gi]);
                        gi++;
                    }
            }
        }
        #pragma unroll
        for (int rp = 0; rp < 4; rp++) Dq4[i + rp * P4_] = dq[rp];
    };

    int iA = s4 + tid;
    if (iA < e4) {
        uint4 dA[4], dB[4];
        {
            int i1 = iA + NTHR;
            issueX(iA, 0);
            issueX(i1 < e4 ? i1 : iA, 1);
        }
        if (!FIRST) {
            #pragma unroll
            for (int rp = 0; rp < 4; rp++) dA[rp] = Dq4[iA + rp * P4_];
        }
        while (true) {
            int iB = iA + NTHR;
            bool hasB = iB < e4;
            if (!FIRST) {
                int ld = hasB ? iB : iA;      // dummy reload; value discarded
                #pragma unroll
                for (int rp = 0; rp < 4; rp++) dB[rp] = Dq4[ld + rp * P4_];
            }
            body(iA, 0, dA);
            { int i2 = iA + 2 * NTHR; issueX(i2 < e4 ? i2 : iA, 0); }
            if (!hasB) break;
            int iC = iB + NTHR;
            bool hasC = iC < e4;
            if (!FIRST) {
                int ld = hasC ? iC : iB;
                #pragma unroll
                for (int rp = 0; rp < 4; rp++) dA[rp] = Dq4[ld + rp * P4_];
            }
            body(iB, 1, dB);
            { int i3 = iB + 2 * NTHR; issueX(i3 < e4 ? i3 : iB, 1); }
            if (!hasC) break;
            iA = iC;
        }
        // drain all pending cp.async before the stage area is reused as `red`
        asm volatile("cp.async.wait_group 0;" ::: "memory");
    }

    // ---- flush: half2 -> f32, then smem transpose (stride RSTR) ----
    __syncthreads();   // all cp.async drained block-wide; red reuse safe
    #pragma unroll
    for (int k = 0; k < 8; k++) {
        float2 f = __half22float2(a_s2[k]);
        red[k * RSTR + tid] = f.x + f.y;
    }
    #pragma unroll
    for (int k = 0; k < 24; k++) {
        float2 f = __half22float2(a_x2[k]);
        red[(8 + k) * RSTR + tid] = f.x + f.y;
    }
    #pragma unroll
    for (int k = 0; k < 36; k++) {
        float2 f = __half22float2(a_g2[k]);
        red[(32 + k) * RSTR + tid] = f.x + f.y;
    }
    __syncthreads();
    if (tid < 68) {
        const float* row = &red[tid * RSTR];
        float s0 = 0.f, s1 = 0.f, s2 = 0.f, s3 = 0.f;
        #pragma unroll 8
        for (int t = 0; t < NTHR; t += 4) {
            s0 += row[t]; s1 += row[t + 1]; s2 += row[t + 2]; s3 += row[t + 3];
        }
        atomicAdd(&dst[tid], (s0 + s1) + (s2 + s3));
    }
}

__global__ void __launch_bounds__(NTHR, 3)
k_all(const float* __restrict__ X, const float* __restrict__ Sin,
      const float* __restrict__ gamma_, const float* __restrict__ lam_,
      float* __restrict__ out) {
    extern __shared__ float red[];           // [68 * RSTR]; doubles as X stage area
    const int tid   = threadIdx.x;
    const int b     = blockIdx.x;
    const int n     = b / BPN;
    const int local = b % BPN;
    const int s4    = (P4_ * local) / BPN;
    const int e4    = (P4_ * (local + 1)) / BPN;
    const int lane  = tid & 31, wid = tid >> 5;

    __shared__ float sS[24], sMX[24], f_own[8], cn_own[8], acc_own[8], x0c[3];
    __shared__ float sh_tauD, sh_lam, sh_gam;
    __shared__ float s_scl[64], s_sums[64], s_gt[64], s_tr[64];
    __shared__ float s_gram[8][8][8], s_x0[24], s_G[192], s_Sg[24], s_n3[8], s_tauS;
    __shared__ float sStS[64];
    __shared__ float sred[12];

    if (tid < 24) sS[tid] = Sin[tid];
    if (tid == 24) sh_gam = fabsf(gamma_[0]);
    if (tid == 25) sh_lam = fabsf(lam_[0]);
    if (tid < 8) { f_own[tid] = 0.f; acc_own[tid] = 0.f; }

    const float4* Xp = reinterpret_cast<const float4*>(X) + (size_t)n * 3 * P4_;
    uint4* Dq4 = g_dt4 + (size_t)n * 4 * P4_;
    float4* Dpout = reinterpret_cast<float4*>(out + 48) + (size_t)n * 8 * P4_;

    // ---- meanX partials over own range ----
    {
        float m0 = 0.f, m1 = 0.f, m2 = 0.f;
        for (int i = s4 + tid; i < e4; i += NTHR) {
            float4 a = Xp[i], bb = Xp[i + P4_], c = Xp[i + 2 * P4_];
            m0 += a.x + a.y + a.z + a.w;
            m1 += bb.x + bb.y + bb.z + bb.w;
            m2 += c.x + c.y + c.z + c.w;
        }
        #pragma unroll
        for (int o = 16; o; o >>= 1) {
            m0 += __shfl_xor_sync(~0u, m0, o);
            m1 += __shfl_xor_sync(~0u, m1, o);
            m2 += __shfl_xor_sync(~0u, m2, o);
        }
        if (lane == 0) { sred[wid * 3 + 0] = m0; sred[wid * 3 + 1] = m1; sred[wid * 3 + 2] = m2; }
        __syncthreads();
        if (tid < 3) {
            float s = 0.f;
            #pragma unroll
            for (int w = 0; w < 4; w++) s += sred[w * 3 + tid];
            g_meanx[b * 3 + tid] = s;
        }
    }

    gridsync();   // meanx partials visible (stats zeroed by k_init0)

    if (tid < 24) {
        int nn = tid / 3, cc = tid % 3;
        float s = 0.f;
        for (int j = 0; j < BPN; j++) s += g_meanx[(nn * BPN + j) * 3 + cc];
        sMX[tid] = s;
    }
    __syncthreads();
    const float lam = sh_lam, gam = sh_gam;

    do_iterA(tid, n, sS, sMX, f_own, acc_own, cn_own, sStS, x0c, &sh_tauD, lam, gam);

    for (int it = 0; it < 3; it++) {
        float* dst = &g_stats[it * 544 + n * 68];
        if (it == 0) run_pass<1>(Xp, Dq4, red, s4, e4, tid, sS, f_own, cn_own, sh_tauD, dst);
        else         run_pass<0>(Xp, Dq4, red, s4, e4, tid, sS, f_own, cn_own, sh_tauD, dst);

        gridsync();   // stats of this iteration complete

        // ================= iterB (redundant per block) =================
        {
            const int last = (it == 2);
            const float* st = &g_stats[it * 544];
            const float tauD = sh_tauD;
            if (tid < 64) {
                int nn = tid >> 3, r = tid & 7;
                float gu = st[nn * 68 + 32 + triIdx(r, r)];
                float L2 = sqrtf(gu);
                float t = L2 - lam * tauD * sqrtf(sStS[r * 8 + r]);
                float scl = fmaxf(t, 0.f) / L2 + EPS_;        // faithful to source
                s_scl[tid] = scl;
                float su = scl * st[nn * 68 + r];
                s_sums[tid] = su;
                s_gt[tid] = gam * su + scl * L2;
                s_tr[tid] = scl * scl * gu;
            }
            __syncthreads();
            for (int idx = tid; idx < 512; idx += NTHR) {
                int nn = idx >> 6, r = (idx >> 3) & 7, r2 = idx & 7;
                int lo = min(r, r2), hi = max(r, r2);
                s_gram[nn][r][r2] = s_scl[nn * 8 + r] * s_scl[nn * 8 + r2] *
                                    st[nn * 68 + 32 + triIdx(lo, hi)];
            }
            __syncthreads();
            if (tid < 24) {
                int nn = tid / 3, c = tid % 3;
                float a = sMX[tid];
                #pragma unroll
                for (int r = 0; r < 8; r++) a += sS[c * 8 + r] * s_sums[nn * 8 + r];
                a *= (1.f / (float)P_);
                s_x0[tid] = a;
                if (last && b == 0) out[tid] = a;
            }
            if (tid == 64) {
                float s = 0.f;
                for (int k = 0; k < 64; k++) s += s_tr[k];
                s_tauS = 8.f / s;
            }
            __syncthreads();
            for (int idx = tid; idx < 192; idx += NTHR) {
                int nn = idx / 24, c = (idx / 8) % 3, r = idx & 7;
                float g = s_scl[nn * 8 + r] * st[nn * 68 + 8 + c * 8 + r];
                #pragma unroll
                for (int r2 = 0; r2 < 8; r2++) g += sS[c * 8 + r2] * s_gram[nn][r2][r];
                g -= s_x0[nn * 3 + c] * s_sums[nn * 8 + r];
                s_G[idx] = g;
            }
            __syncthreads();
            if (tid < 24) {
                int c = tid / 8, r = tid & 7;
                float mg = 0.f;
                #pragma unroll
                for (int nn = 0; nn < 8; nn++) mg += s_G[nn * 24 + c * 8 + r];
                mg *= 0.125f;
                s_Sg[tid] = sS[c * 8 + r] - s_tauS * mg;
            }
            __syncthreads();
            if (tid < 8) {
                int r = tid;
                float dn = 0.f;
                #pragma unroll
                for (int nn = 0; nn < 8; nn++) dn += s_gt[nn * 8 + r];
                dn *= 0.125f;
                float n2 = 0.f;
                #pragma unroll
                for (int c = 0; c < 3; c++) n2 += s_Sg[c * 8 + r] * s_Sg[c * 8 + r];
                n2 = sqrtf(n2);
                float t = n2 - lam * s_tauS * dn;
                float sclS = fmaxf(t, 0.f) / (n2 + EPS_);
                float sn[3]; float n3 = 0.f;
                #pragma unroll
                for (int c = 0; c < 3; c++) { sn[c] = s_Sg[c * 8 + r] * sclS; n3 += sn[c] * sn[c]; }
                n3 = sqrtf(n3);
                s_n3[r] = n3;
                float inv = 1.f / (n3 + EPS_);
                #pragma unroll
                for (int c = 0; c < 3; c++) {
                    float nv = sn[c] * inv;
                    sS[c * 8 + r] = nv;
                    if (last && b == 0) out[24 + c * 8 + r] = nv;
                }
            }
            __syncthreads();
            if (tid < 8) {
                f_own[tid]   = s_scl[n * 8 + tid] * (s_n3[tid] + EPS_);
                acc_own[tid] = st[n * 68 + tid];
            }
            __syncthreads();
            if (!last)
                do_iterA(tid, n, sS, sMX, f_own, acc_own, cn_own, sStS, x0c, &sh_tauD, lam, gam);
        }
    }

    // ====== final scale pass: out = f * fp16(Dt_it2), ping-pong prefetch. ======
    {
        float fs[8];
        #pragma unroll
        for (int r = 0; r < 8; r++) fs[r] = f_own[r];
        auto sbody = [&](int i, uint4* dq) {
            #pragma unroll
            for (int rp = 0; rp < 4; rp++) {
                float4 va = h4tof4(dq[rp].x, dq[rp].y);
                float4 vb = h4tof4(dq[rp].z, dq[rp].w);
                float fa = fs[2 * rp], fb = fs[2 * rp + 1];
                va.x *= fa; va.y *= fa; va.z *= fa; va.w *= fa;
                vb.x *= fb; vb.y *= fb; vb.z *= fb; vb.w *= fb;
                __stcs(&Dpout[i + (2 * rp) * P4_], va);
                __stcs(&Dpout[i + (2 * rp + 1) * P4_], vb);
            }
        };
        int iA = s4 + tid;
        if (iA < e4) {
            uint4 dA[4], dB[4];
            #pragma unroll
            for (int rp = 0; rp < 4; rp++) dA[rp] = Dq4[iA + rp * P4_];
            while (true) {
                int iB = iA + NTHR;
                bool hasB = iB < e4;
                {
                    int ld = hasB ? iB : iA;
                    #pragma unroll
                    for (int rp = 0; rp < 4; rp++) dB[rp] = Dq4[ld + rp * P4_];
                }
                sbody(iA, dA);
                if (!hasB) break;
                int iC = iB + NTHR;
                bool hasC = iC < e4;
                {
                    int ld = hasC ? iC : iB;
                    #pragma unroll
                    for (int rp = 0; rp < 4; rp++) dA[rp] = Dq4[ld + rp * P4_];
                }
                sbody(iB, dB);
                if (!hasC) break;
                iA = iC;
            }
        }
    }
}

extern "C" void kernel_launch(void* const* d_in, const int* in_sizes, int n_in,
                              void* d_out, int out_size) {
    const float* X     = (const float*)d_in[0];
    const float* S     = (const float*)d_in[1];
    const float* gamma = (const float*)d_in[2];
    const float* lam   = (const float*)d_in[3];
    float* out = (float*)d_out;
    const int smem_bytes = 68 * RSTR * 4;    // 35,088 B (reduction buffer / X stages)
    k_init0<<<1, 512>>>();                   // deterministic state reset every launch
    k_all<<<NB, NTHR, smem_bytes>>>(X, S, gamma, lam, out);
}

// round 17
// speedup vs baseline: 1.0781x; 1.0276x over previous
#include <cuda_runtime.h>
#include <cuda_fp16.h>
#include <math.h>

// Problem constants: N=8, C=3, R=8, P=512*512, n_iter=3
#define P_    262144
#define P4_   65536        // float4 / point-group count per plane
#define EPS_  1e-10f
#define NB    440          // total blocks (8 n-groups x 55); 3/SM co-resident
#define BPN   55
#define NTHR  128
#define RSTR  129          // reduction smem stride (conflict-free)

// ---- device globals (no allocations allowed) ----
__device__ float    g_stats[3 * 544];     // per iter, per n: [0,8) sum, [8,32) XD, [32,68) gram-tri
__device__ float    g_meanx[NB * 3];
__device__ unsigned g_count = 0;
__device__ unsigned g_sense = 0;
// fp16 Dt scratch: [n][rp][point4] planes; uint4 = 4 points x (r=2rp, r=2rp+1)
__device__ uint4    g_dt4[(size_t)32 * P4_];

__device__ __forceinline__ int triIdx(int r, int r2) {   // r <= r2
    return r * 8 - (r * (r - 1)) / 2 + (r2 - r);
}
__device__ __forceinline__ float getc(const float4& v, int j) {
    return j == 0 ? v.x : j == 1 ? v.y : j == 2 ? v.z : v.w;
}
__device__ __forceinline__ float hsel(unsigned u, int hi) {
    __half2 h = *reinterpret_cast<__half2*>(&u);
    return hi ? __high2float(h) : __low2float(h);
}
__device__ __forceinline__ unsigned h2bits(__half2 h) {
    return *reinterpret_cast<unsigned*>(&h);
}
__device__ __forceinline__ float4 h4tof4(unsigned a_, unsigned b_) {
    __half2 a = *reinterpret_cast<__half2*>(&a_);
    __half2 b = *reinterpret_cast<__half2*>(&b_);
    float2 fa = __half22float2(a), fb = __half22float2(b);
    return make_float4(fa.x, fa.y, fb.x, fb.y);
}
__device__ __forceinline__ unsigned ld_acq(unsigned* p) {
    unsigned v;
    asm volatile("ld.acquire.gpu.u32 %0, [%1];" : "=r"(v) : "l"(p) : "memory");
    return v;
}
// grid-wide sense-reversal barrier; all NB blocks co-resident by construction.
// Replay-safe: g_count returns to 0 after each completed barrier; sense is
// compared relatively, so a monotonically increasing g_sense is harmless.
__device__ __forceinline__ void gridsync() {
    __threadfence();
    __syncthreads();
    if (threadIdx.x == 0) {
        unsigned s0 = ld_acq(&g_sense);
        unsigned old = atomicAdd(&g_count, 1u);
        if (old == NB - 1) {
            atomicExch(&g_count, 0u);
            __threadfence();
            atomicAdd(&g_sense, 1u);
        } else {
            while (ld_acq(&g_sense) == s0) __nanosleep(64);
        }
    }
    __syncthreads();
}

// iterA: StS, tauD, x0(own n), cnst(own n). Redundant per block.
__device__ __forceinline__ void do_iterA(int tid, int n,
        const float* sS, const float* sMX, const float* f_own, const float* acc_own,
        float* cn_own, float* sStS, float* x0c, float* sh_tauD, float lam, float gam) {
    if (tid < 64) {
        int r = tid >> 3, r2 = tid & 7;
        float a = 0.f;
        #pragma unroll
        for (int c = 0; c < 3; c++) a += sS[c * 8 + r] * sS[c * 8 + r2];
        sStS[tid] = a;
    }
    __syncthreads();
    if (tid == 0) {
        float s = 0.f;
        #pragma unroll
        for (int r = 0; r < 8; r++) s += sStS[r * 8 + r];
        *sh_tauD = 1.f / s;
    }
    __syncthreads();
    float tauD = *sh_tauD;
    if (tid < 3) {
        float acc = sMX[n * 3 + tid];
        #pragma unroll
        for (int r = 0; r < 8; r++) acc += sS[tid * 8 + r] * f_own[r] * acc_own[r];
        x0c[tid] = acc * (1.f / (float)P_);
    }
    __syncthreads();
    if (tid < 8) {
        int r = tid;
        float bb = 0.f;
        #pragma unroll
        for (int c = 0; c < 3; c++) bb += sS[c * 8 + r] * x0c[c];
        cn_own[r] = tauD * bb - lam * gam * tauD * sqrtf(sStS[r * 8 + r]);
    }
    __syncthreads();
}

// ---------------------------------------------------------------------------
// run_pass: fused D-update + prox + stats.
//   X pipelined global->smem via cp.async (2 stages, zero register cost),
//   Dt fp16 uint4 planes with register ping-pong prefetch, in-place output
//   pack, half2 pairwise stats, sqrt(tauD) fold.
//   FIRST=1: no Dt read (dq = pure output staging).
// ---------------------------------------------------------------------------
template<int FIRST>
__device__ __forceinline__ void run_pass(
    const float4* __restrict__ Xp, uint4* __restrict__ Dq4,
    float* red, int s4, int e4, int tid,
    const float* sS, const float* f_own, const float* cn_own, float tauD,
    float* dst)
{
    float4* sx = reinterpret_cast<float4*>(red);    // X stage area (overlaid on red)

    float Sp[24], fr[8], cn[8];
    const float sq = sqrtf(tauD);
    #pragma unroll
    for (int k = 0; k < 24; k++) Sp[k] = sq * sS[k];
    #pragma unroll
    for (int r = 0; r < 8; r++) { fr[r] = f_own[r]; cn[r] = cn_own[r]; }

    const __half2 hz = __floats2half2_rn(0.f, 0.f);
    __half2 a_s2[8], a_x2[24], a_g2[36];
    #pragma unroll
    for (int k = 0; k < 8; k++)  a_s2[k] = hz;
    #pragma unroll
    for (int k = 0; k < 24; k++) a_x2[k] = hz;
    #pragma unroll
    for (int k = 0; k < 36; k++) a_g2[k] = hz;

    auto issueX = [&](int i, int stage) {
        #pragma unroll
        for (int c = 0; c < 3; c++) {
            unsigned dstA = (unsigned)__cvta_generic_to_shared(
                &sx[(stage * 3 + c) * NTHR + tid]);
            asm volatile("cp.async.cg.shared.global [%0], [%1], 16;"
                         :: "r"(dstA), "l"(&Xp[i + c * P4_]) : "memory");
        }
        asm volatile("cp.async.commit_group;" ::: "memory");
    };

    // body: compute one point-group from staged X + prefetched Dt; dq is
    // overwritten in place with packed fp16 outputs.
    auto body = [&](int i, int stage, uint4* dq) {
        asm volatile("cp.async.wait_group 1;" ::: "memory");
        float4 xv0 = sx[(stage * 3 + 0) * NTHR + tid];
        float4 xv1 = sx[(stage * 3 + 1) * NTHR + tid];
        float4 xv2 = sx[(stage * 3 + 2) * NTHR + tid];
        float vprev[8], xprev0, xprev1, xprev2;
        #pragma unroll
        for (int j = 0; j < 4; j++) {
            const float x0 = getc(xv0, j), x1 = getc(xv1, j), x2 = getc(xv2, j);
            float tt0 = sq * x0, tt1 = sq * x1, tt2 = sq * x2;
            float de[8], v[8];
            if (!FIRST) {
                #pragma unroll
                for (int rp = 0; rp < 4; rp++) {
                    unsigned wa = (j < 2) ? dq[rp].x : dq[rp].y;
                    unsigned wb = (j < 2) ? dq[rp].z : dq[rp].w;
                    de[2 * rp]     = fr[2 * rp]     * hsel(wa, j & 1);
                    de[2 * rp + 1] = fr[2 * rp + 1] * hsel(wb, j & 1);
                }
                #pragma unroll
                for (int r = 0; r < 8; r++) {
                    tt0 += Sp[r] * de[r];
                    tt1 += Sp[8 + r] * de[r];
                    tt2 += Sp[16 + r] * de[r];
                }
            }
            #pragma unroll
            for (int r = 0; r < 8; r++) {
                float w = FIRST ? cn[r] : (de[r] + cn[r]);
                float val = w - Sp[r] * tt0 - Sp[8 + r] * tt1 - Sp[16 + r] * tt2;
                v[r] = fmaxf(val, 0.f);
            }
            if ((j & 1) == 0) {
                #pragma unroll
                for (int r = 0; r < 8; r++) vprev[r] = v[r];
                xprev0 = x0; xprev1 = x1; xprev2 = x2;
            } else {
                __half2 p[8];
                #pragma unroll
                for (int r = 0; r < 8; r++) p[r] = __floats2half2_rn(vprev[r], v[r]);
                #pragma unroll
                for (int rp = 0; rp < 4; rp++) {
                    unsigned pa = h2bits(p[2 * rp]);
                    unsigned pb = h2bits(p[2 * rp + 1]);
                    if (j == 1) { dq[rp].x = pa; dq[rp].z = pb; }
                    else        { dq[rp].y = pa; dq[rp].w = pb; }
                }
                __half2 px0 = __floats2half2_rn(xprev0, x0);
                __half2 px1 = __floats2half2_rn(xprev1, x1);
                __half2 px2 = __floats2half2_rn(xprev2, x2);
                #pragma unroll
                for (int r = 0; r < 8; r++) {
                    a_s2[r]      = __hadd2(a_s2[r], p[r]);
                    a_x2[r]      = __hfma2(px0, p[r], a_x2[r]);
                    a_x2[8 + r]  = __hfma2(px1, p[r], a_x2[8 + r]);
                    a_x2[16 + r] = __hfma2(px2, p[r], a_x2[16 + r]);
                }
                int gi = 0;
                #pragma unroll
                for (int r = 0; r < 8; r++)
                    #pragma unroll
                    for (int r2 = r; r2 < 8; r2++) {
                        a_g2[gi] = __hfma2(p[r], p[r2], a_g2[gi]);
                        gi++;
                    }
            }
        }
        #pragma unroll
        for (int rp = 0; rp < 4; rp++) Dq4[i + rp * P4_] = dq[rp];
    };

    int iA = s4 + tid;
    if (iA < e4) {
        uint4 dA[4], dB[4];
        {
            int i1 = iA + NTHR;
            issueX(iA, 0);
            issueX(i1 < e4 ? i1 : iA, 1);
        }
        if (!FIRST) {
            #pragma unroll
            for (int rp = 0; rp < 4; rp++) dA[rp] = Dq4[iA + rp * P4_];
        }
        while (true) {
            int iB = iA + NTHR;
            bool hasB = iB < e4;
            if (!FIRST) {
                int ld = hasB ? iB : iA;      // dummy reload; value discarded
                #pragma unroll
                for (int rp = 0; rp < 4; rp++) dB[rp] = Dq4[ld + rp * P4_];
            }
            body(iA, 0, dA);
            { int i2 = iA + 2 * NTHR; issueX(i2 < e4 ? i2 : iA, 0); }
            if (!hasB) break;
            int iC = iB + NTHR;
            bool hasC = iC < e4;
            if (!FIRST) {
                int ld = hasC ? iC : iB;
                #pragma unroll
                for (int rp = 0; rp < 4; rp++) dA[rp] = Dq4[ld + rp * P4_];
            }
            body(iB, 1, dB);
            { int i3 = iB + 2 * NTHR; issueX(i3 < e4 ? i3 : iB, 1); }
            if (!hasC) break;
            iA = iC;
        }
        // drain all pending cp.async before the stage area is reused as `red`
        asm volatile("cp.async.wait_group 0;" ::: "memory");
    }

    // ---- flush: half2 -> f32, then smem transpose (stride RSTR) ----
    __syncthreads();   // all cp.async drained block-wide; red reuse safe
    #pragma unroll
    for (int k = 0; k < 8; k++) {
        float2 f = __half22float2(a_s2[k]);
        red[k * RSTR + tid] = f.x + f.y;
    }
    #pragma unroll
    for (int k = 0; k < 24; k++) {
        float2 f = __half22float2(a_x2[k]);
        red[(8 + k) * RSTR + tid] = f.x + f.y;
    }
    #pragma unroll
    for (int k = 0; k < 36; k++) {
        float2 f = __half22float2(a_g2[k]);
        red[(32 + k) * RSTR + tid] = f.x + f.y;
    }
    __syncthreads();
    if (tid < 68) {
        const float* row = &red[tid * RSTR];
        float s0 = 0.f, s1 = 0.f, s2 = 0.f, s3 = 0.f;
        #pragma unroll 8
        for (int t = 0; t < NTHR; t += 4) {
            s0 += row[t]; s1 += row[t + 1]; s2 += row[t + 2]; s3 += row[t + 3];
        }
        atomicAdd(&dst[tid], (s0 + s1) + (s2 + s3));
    }
}

__global__ void __launch_bounds__(NTHR, 3)
k_all(const float* __restrict__ X, const float* __restrict__ Sin,
      const float* __restrict__ gamma_, const float* __restrict__ lam_,
      float* __restrict__ out) {
    extern __shared__ float red[];           // [68 * RSTR]; doubles as X stage area
    const int tid   = threadIdx.x;
    const int b     = blockIdx.x;
    const int n     = b / BPN;
    const int local = b % BPN;
    const int s4    = (P4_ * local) / BPN;
    const int e4    = (P4_ * (local + 1)) / BPN;
    const int lane  = tid & 31, wid = tid >> 5;

    __shared__ float sS[24], sMX[24], f_own[8], cn_own[8], acc_own[8], x0c[3];
    __shared__ float sh_tauD, sh_lam, sh_gam;
    __shared__ float s_scl[64], s_sums[64], s_gt[64], s_tr[64];
    __shared__ float s_gram[8][8][8], s_x0[24], s_G[192], s_Sg[24], s_n3[8], s_tauS;
    __shared__ float sStS[64];
    __shared__ float sred[12];

    if (tid < 24) sS[tid] = Sin[tid];
    if (tid == 24) sh_gam = fabsf(gamma_[0]);
    if (tid == 25) sh_lam = fabsf(lam_[0]);
    if (tid < 8) { f_own[tid] = 0.f; acc_own[tid] = 0.f; }
    { int idx = b * NTHR + tid; if (idx < 3 * 544) g_stats[idx] = 0.f; }

    const float4* Xp = reinterpret_cast<const float4*>(X) + (size_t)n * 3 * P4_;
    uint4* Dq4 = g_dt4 + (size_t)n * 4 * P4_;
    float4* Dpout = reinterpret_cast<float4*>(out + 48) + (size_t)n * 8 * P4_;

    // ---- meanX partials over own range ----
    {
        float m0 = 0.f, m1 = 0.f, m2 = 0.f;
        for (int i = s4 + tid; i < e4; i += NTHR) {
            float4 a = Xp[i], bb = Xp[i + P4_], c = Xp[i + 2 * P4_];
            m0 += a.x + a.y + a.z + a.w;
            m1 += bb.x + bb.y + bb.z + bb.w;
            m2 += c.x + c.y + c.z + c.w;
        }
        #pragma unroll
        for (int o = 16; o; o >>= 1) {
            m0 += __shfl_xor_sync(~0u, m0, o);
            m1 += __shfl_xor_sync(~0u, m1, o);
            m2 += __shfl_xor_sync(~0u, m2, o);
        }
        if (lane == 0) { sred[wid * 3 + 0] = m0; sred[wid * 3 + 1] = m1; sred[wid * 3 + 2] = m2; }
        __syncthreads();
        if (tid < 3) {
            float s = 0.f;
            #pragma unroll
            for (int w = 0; w < 4; w++) s += sred[w * 3 + tid];
            g_meanx[b * 3 + tid] = s;
        }
    }

    gridsync();   // zeroed stats + meanx partials visible

    if (tid < 24) {
        int nn = tid / 3, cc = tid % 3;
        float s = 0.f;
        for (int j = 0; j < BPN; j++) s += g_meanx[(nn * BPN + j) * 3 + cc];
        sMX[tid] = s;
    }
    __syncthreads();
    const float lam = sh_lam, gam = sh_gam;

    do_iterA(tid, n, sS, sMX, f_own, acc_own, cn_own, sStS, x0c, &sh_tauD, lam, gam);

    for (int it = 0; it < 3; it++) {
        float* dst = &g_stats[it * 544 + n * 68];
        if (it == 0) run_pass<1>(Xp, Dq4, red, s4, e4, tid, sS, f_own, cn_own, sh_tauD, dst);
        else         run_pass<0>(Xp, Dq4, red, s4, e4, tid, sS, f_own, cn_own, sh_tauD, dst);

        gridsync();   // stats of this iteration complete

        // ================= iterB (redundant per block) =================
        {
            const int last = (it == 2);
            const float* st = &g_stats[it * 544];
            const float tauD = sh_tauD;
            if (tid < 64) {
                int nn = tid >> 3, r = tid & 7;
                float gu = st[nn * 68 + 32 + triIdx(r, r)];
                float L2 = sqrtf(gu);
                float t = L2 - lam * tauD * sqrtf(sStS[r * 8 + r]);
                float scl = fmaxf(t, 0.f) / L2 + EPS_;        // faithful to source
                s_scl[tid] = scl;
                float su = scl * st[nn * 68 + r];
                s_sums[tid] = su;
                s_gt[tid] = gam * su + scl * L2;
                s_tr[tid] = scl * scl * gu;
            }
            __syncthreads();
            for (int idx = tid; idx < 512; idx += NTHR) {
                int nn = idx >> 6, r = (idx >> 3) & 7, r2 = idx & 7;
                int lo = min(r, r2), hi = max(r, r2);
                s_gram[nn][r][r2] = s_scl[nn * 8 + r] * s_scl[nn * 8 + r2] *
                                    st[nn * 68 + 32 + triIdx(lo, hi)];
            }
            __syncthreads();
            if (tid < 24) {
                int nn = tid / 3, c = tid % 3;
                float a = sMX[tid];
                #pragma unroll
                for (int r = 0; r < 8; r++) a += sS[c * 8 + r] * s_sums[nn * 8 + r];
                a *= (1.f / (float)P_);
                s_x0[tid] = a;
                if (last && b == 0) out[tid] = a;
            }
            if (tid == 64) {
                float s = 0.f;
                for (int k = 0; k < 64; k++) s += s_tr[k];
                s_tauS = 8.f / s;
            }
            __syncthreads();
            for (int idx = tid; idx < 192; idx += NTHR) {
                int nn = idx / 24, c = (idx / 8) % 3, r = idx & 7;
                float g = s_scl[nn * 8 + r] * st[nn * 68 + 8 + c * 8 + r];
                #pragma unroll
                for (int r2 = 0; r2 < 8; r2++) g += sS[c * 8 + r2] * s_gram[nn][r2][r];
                g -= s_x0[nn * 3 + c] * s_sums[nn * 8 + r];
                s_G[idx] = g;
            }
            __syncthreads();
            if (tid < 24) {
                int c = tid / 8, r = tid & 7;
                float mg = 0.f;
                #pragma unroll
                for (int nn = 0; nn < 8; nn++) mg += s_G[nn * 24 + c * 8 + r];
                mg *= 0.125f;
                s_Sg[tid] = sS[c * 8 + r] - s_tauS * mg;
            }
            __syncthreads();
            if (tid < 8) {
                int r = tid;
                float dn = 0.f;
                #pragma unroll
                for (int nn = 0; nn < 8; nn++) dn += s_gt[nn * 8 + r];
                dn *= 0.125f;
                float n2 = 0.f;
                #pragma unroll
                for (int c = 0; c < 3; c++) n2 += s_Sg[c * 8 + r] * s_Sg[c * 8 + r];
                n2 = sqrtf(n2);
                float t = n2 - lam * s_tauS * dn;
                float sclS = fmaxf(t, 0.f) / (n2 + EPS_);
                float sn[3]; float n3 = 0.f;
                #pragma unroll
                for (int c = 0; c < 3; c++) { sn[c] = s_Sg[c * 8 + r] * sclS; n3 += sn[c] * sn[c]; }
                n3 = sqrtf(n3);
                s_n3[r] = n3;
                float inv = 1.f / (n3 + EPS_);
                #pragma unroll
                for (int c = 0; c < 3; c++) {
                    float nv = sn[c] * inv;
                    sS[c * 8 + r] = nv;
                    if (last && b == 0) out[24 + c * 8 + r] = nv;
                }
            }
            __syncthreads();
            if (tid < 8) {
                f_own[tid]   = s_scl[n * 8 + tid] * (s_n3[tid] + EPS_);
                acc_own[tid] = st[n * 68 + tid];
            }
            __syncthreads();
            if (!last)
                do_iterA(tid, n, sS, sMX, f_own, acc_own, cn_own, sStS, x0c, &sh_tauD, lam, gam);
        }
    }

    // ====== final scale pass: out = f * fp16(Dt_it2), ping-pong prefetch. ======
    {
        float fs[8];
        #pragma unroll
        for (int r = 0; r < 8; r++) fs[r] = f_own[r];
        auto sbody = [&](int i, uint4* dq) {
            #pragma unroll
            for (int rp = 0; rp < 4; rp++) {
                float4 va = h4tof4(dq[rp].x, dq[rp].y);
                float4 vb = h4tof4(dq[rp].z, dq[rp].w);
                float fa = fs[2 * rp], fb = fs[2 * rp + 1];
                va.x *= fa; va.y *= fa; va.z *= fa; va.w *= fa;
                vb.x *= fb; vb.y *= fb; vb.z *= fb; vb.w *= fb;
                __stcs(&Dpout[i + (2 * rp) * P4_], va);
                __stcs(&Dpout[i + (2 * rp + 1) * P4_], vb);
            }
        };
        int iA = s4 + tid;
        if (iA < e4) {
            uint4 dA[4], dB[4];
            #pragma unroll
            for (int rp = 0; rp < 4; rp++) dA[rp] = Dq4[iA + rp * P4_];
            while (true) {
                int iB = iA + NTHR;
                bool hasB = iB < e4;
                {
                    int ld = hasB ? iB : iA;
                    #pragma unroll
                    for (int rp = 0; rp < 4; rp++) dB[rp] = Dq4[ld + rp * P4_];
                }
                sbody(iA, dA);
                if (!hasB) break;
                int iC = iB + NTHR;
                bool hasC = iC < e4;
                {
                    int ld = hasC ? iC : iB;
                    #pragma unroll
                    for (int rp = 0; rp < 4; rp++) dA[rp] = Dq4[ld + rp * P4_];
                }
                sbody(iB, dB);
                if (!hasC) break;
                iA = iC;
            }
        }
    }
}

extern "C" void kernel_launch(void* const* d_in, const int* in_sizes, int n_in,
                              void* d_out, int out_size) {
    const float* X     = (const float*)d_in[0];
    const float* S     = (const float*)d_in[1];
    const float* gamma = (const float*)d_in[2];
    const float* lam   = (const float*)d_in[3];
    float* out = (float*)d_out;
    const int smem_bytes = 68 * RSTR * 4;    // 35,088 B (reduction buffer / X stages)
    k_all<<<NB, NTHR, smem_bytes>>>(X, S, gamma, lam, out);
}